// round 12
// baseline (speedup 1.0000x reference)
#include <cuda_runtime.h>
#include <math.h>

// ------------------------ problem constants ------------------------
#define Bc      2
#define NEGc    16
#define Nc      10000
#define Ec      80000
#define Dc      128
#define Lc      3
#define Kc      1000
#define BNc     20000
#define NUMRELc 237
#define EPSc    1e-5f
#define DMAXc   6016     // max dirty nodes: 4 boundary + 3*2000
#define UMAXc   2048     // max updated nodes per layer (<= B*K = 2000)
#define SCORE_BLKS 752   // DMAXc/8
#define FILL_BLKS  157   // ceil(BNc/128)
#define AGS     20       // shared row stride (floats): 16B-aligned, reduced bank conflicts

// ------------------------ device scratch (static, no runtime alloc) ------------------------
__device__ float g_hidden[BNc * Dc];
__device__ float g_Q[BNc * Dc];          // never bulk-zeroed: every read preceded by same-layer write
__device__ float g_score[BNc];
__device__ int   g_dirty[BNc];
__device__ unsigned char g_sel[BNc];
__device__ int   g_indeg[Nc];
__device__ int   g_outdeg[Nc];
__device__ int   g_inoff[Nc + 1];
__device__ int   g_cursor[Nc];
__device__ int   g_insrc[Ec];
__device__ int   g_Dlist[DMAXc];
__device__ int   g_Dcnt;
__device__ int   g_Ulist[UMAXc];
__device__ int   g_UcntA[Lc];
__device__ unsigned long long g_sumlogA[Lc];
__device__ float g_rel[Bc * Dc];
__device__ float g_rellin[Bc * Dc];
__device__ float g_szero;
__device__ int   g_tidx[Bc * NEGc];

// ------------------------ helpers ------------------------
__device__ __forceinline__ unsigned map_sc(float f) {
    unsigned u = __float_as_uint(f);
    if (u == 0x80000000u) u = 0u;                      // normalize -0 -> +0
    return (u & 0x80000000u) ? ~u : (u | 0x80000000u); // monotone order-preserving map
}

// packed fp32x2 (Blackwell): two IEEE fp32 FMAs per instruction, bit-identical lanes
__device__ __forceinline__ unsigned long long pk(float lo, float hi) {
    unsigned long long r;
    asm("mov.b64 %0, {%1, %2};" : "=l"(r) : "r"(__float_as_uint(lo)), "r"(__float_as_uint(hi)));
    return r;
}
__device__ __forceinline__ void upk(unsigned long long v, float& lo, float& hi) {
    unsigned a, b;
    asm("mov.b64 {%0, %1}, %2;" : "=r"(a), "=r"(b) : "l"(v));
    lo = __uint_as_float(a); hi = __uint_as_float(b);
}
__device__ __forceinline__ unsigned long long ffma2(unsigned long long a, unsigned long long b,
                                                    unsigned long long c) {
    unsigned long long d;
    asm("fma.rn.f32x2 %0, %1, %2, %3;" : "=l"(d) : "l"(a), "l"(b), "l"(c));
    return d;
}

// ------------------------ init ------------------------
__global__ void k_zero() {
    int i = blockIdx.x * 256 + threadIdx.x;
    if (i < BNc * Dc) g_hidden[i] = 0.f;
    if (i < BNc)      { g_score[i] = 0.f; g_dirty[i] = 0; }
    if (i < Nc)       { g_indeg[i] = 0; g_outdeg[i] = 0; }
    if (i == 0)       g_Dcnt = 0;
    if (i < Lc)       { g_UcntA[i] = 0; g_sumlogA[i] = 0ull; }
}

__global__ void k_deg(const int* __restrict__ ei) {
    int i = blockIdx.x * 256 + threadIdx.x;
    if (i < Ec) {
        atomicAdd(&g_outdeg[ei[i]], 1);
        atomicAdd(&g_indeg[ei[Ec + i]], 1);
    }
}

__global__ void k_scan() {   // exclusive scan of indeg -> inoff (single block, 1024 thr)
    __shared__ int tot[1024];
    int t = threadIdx.x;
    const int CH = 10;
    int loc[CH];
    int s = 0;
#pragma unroll
    for (int j = 0; j < CH; j++) {
        int idx = t * CH + j;
        int v = (idx < Nc) ? g_indeg[idx] : 0;
        loc[j] = s; s += v;
    }
    tot[t] = s;
    __syncthreads();
    for (int off = 1; off < 1024; off <<= 1) {
        int v = (t >= off) ? tot[t - off] : 0;
        __syncthreads();
        tot[t] += v;
        __syncthreads();
    }
    int ex = tot[t] - s;
#pragma unroll
    for (int j = 0; j < CH; j++) {
        int idx = t * CH + j;
        if (idx < Nc) { g_inoff[idx] = ex + loc[j]; g_cursor[idx] = 0; }
    }
    if (t == 1023) g_inoff[Nc] = tot[1023];
}

__global__ void k_fill(const int* __restrict__ ei) {
    int i = blockIdx.x * 256 + threadIdx.x;
    if (i < Ec) {
        int d = ei[Ec + i];
        int pos = atomicAdd(&g_cursor[d], 1);
        g_insrc[g_inoff[d] + pos] = ei[i];
    }
}

// ------------------------ prep phase 1: misc + rel_lin (3 blocks) ------------------------
__global__ void __launch_bounds__(128) k_prep1(const int* __restrict__ hI, const int* __restrict__ rI,
                        const int* __restrict__ tI, const float* __restrict__ HS,
                        const float* __restrict__ RE, const float* __restrict__ linW,
                        const float* __restrict__ linb, const float* __restrict__ m1b,
                        const float* __restrict__ m2W, const float* __restrict__ m2b) {
    int k = threadIdx.x, blk = blockIdx.x;
    __shared__ int hh[Bc], tt[Bc], rr[Bc], isT[Bc];
    __shared__ float rl[Dc];
    __shared__ float red[Dc];

    if (k < Bc) {
        int b = k;
        int t_neg = 1;
        int h0 = hI[b * NEGc];
        for (int j = 1; j < NEGc; j++) if (hI[b * NEGc + j] != h0) t_neg = 0;
        isT[b] = t_neg;
        hh[b] = t_neg ? h0 : tI[b * NEGc];
        tt[b] = t_neg ? tI[b * NEGc] : h0;
        rr[b] = t_neg ? rI[b * NEGc] : (rI[b * NEGc] + NUMRELc);
    }
    __syncthreads();

    if (blk == 0) {
        for (int idx = k; idx < Bc * NEGc; idx += Dc) {
            int b = idx / NEGc;
            int tv = isT[b] ? tI[idx] : hI[idx];
            g_tidx[idx] = tv + b * Nc;
        }
        for (int b = 0; b < Bc; b++) g_rel[b * Dc + k] = RE[rr[b] * Dc + k];
        // reference quirk: h_vals/t_vals both use ROW 0's indices for every batch
        float hv = HS[hh[0] * Dc + k];
        float tv = HS[tt[0] * Dc + k];
        for (int b = 0; b < Bc; b++) g_hidden[(tt[b] + b * Nc) * Dc + k] = tv;
        __syncthreads();
        for (int b = 0; b < Bc; b++) g_hidden[(hh[b] + b * Nc) * Dc + k] = hv;
        if (k == 0) {
            for (int b = 0; b < Bc; b++) {
                int nodes2[2] = { tt[b] + b * Nc, hh[b] + b * Nc };
                for (int q = 0; q < 2; q++) {
                    int v = nodes2[q];
                    if (atomicExch(&g_dirty[v], 1) == 0) {
                        int p = atomicAdd(&g_Dcnt, 1);
                        g_Dlist[p] = v;
                    }
                }
            }
        }
        // s_zero = relu(m1_b) @ m2_W + m2_b
        red[k] = fmaxf(m1b[k], 0.f) * m2W[k];
        __syncthreads();
        for (int s = 64; s > 0; s >>= 1) {
            if (k < s) red[k] += red[k + s];
            __syncthreads();
        }
        if (k == 0) g_szero = red[0] + m2b[0];
    } else {
        int b = blk - 1;
        rl[k] = RE[rr[b] * Dc + k];
        __syncthreads();
        float a = linb[k];
#pragma unroll 8
        for (int j = 0; j < Dc; j++) a += rl[j] * linW[(Dc + j) * Dc + k];
        g_rellin[b * Dc + k] = a;
    }
}

// ------------------------ prep phase 2: initial score per batch (2 blocks) ------------------------
__global__ void __launch_bounds__(128) k_prep2(const int* __restrict__ hI, const int* __restrict__ tI,
                        const float* __restrict__ HS, const float* __restrict__ linW,
                        const float* __restrict__ m1W, const float* __restrict__ m1b,
                        const float* __restrict__ m2W, const float* __restrict__ m2b) {
    int k = threadIdx.x, b = blockIdx.x;
    __shared__ float hvs[Dc], xs[Dc], red[Dc];

    int tn0 = 1, h00 = hI[0];
    for (int j = 1; j < NEGc; j++) if (hI[j] != h00) tn0 = 0;
    int hh0 = tn0 ? h00 : tI[0];
    int tnb = 1, hb0 = hI[b * NEGc];
    for (int j = 1; j < NEGc; j++) if (hI[b * NEGc + j] != hb0) tnb = 0;
    int hhb = tnb ? hb0 : tI[b * NEGc];

    float hv = HS[hh0 * Dc + k];
    hvs[k] = hv;
    __syncthreads();

    float a = g_rellin[b * Dc + k];
#pragma unroll 8
    for (int j = 0; j < Dc; j++) a += hvs[j] * linW[j * Dc + k];
    float x = a * hv;
    xs[k] = x;
    __syncthreads();
    float h2 = m1b[k];
#pragma unroll 8
    for (int j = 0; j < Dc; j++) h2 += xs[j] * m1W[j * Dc + k];
    h2 = fmaxf(h2, 0.f);
    red[k] = h2 * m2W[k];
    __syncthreads();
    for (int s = 64; s > 0; s >>= 1) {
        if (k < s) red[k] += red[k + s];
        __syncthreads();
    }
    if (k == 0) g_score[hhb + b * Nc] = red[0] + m2b[0];
}

// ------------------------ top-K radix select + FUSED selection/list build ------------------------
__global__ void __launch_bounds__(1024) k_topk(int l) {
    extern __shared__ unsigned SC[];            // Nc mapped scores (40000 B)
    __shared__ unsigned hist[256];
    __shared__ unsigned cum[257];
    __shared__ int sh_bsel, sh_remK, sh_done;

    int b = blockIdx.x, tid = threadIdx.x, lane = tid & 31;
    for (int i = tid; i < Nc; i += 1024) SC[i] = map_sc(g_score[b * Nc + i]);
    if (tid == 0) { sh_remK = Kc; sh_done = 0; }
    __syncthreads();

    unsigned long long prefix = 0ull;
    const int S[6] = {56, 48, 40, 32, 8, 0};   // key byte positions (idx bytes 24,16 always 0)

    for (int p = 0; p < 6; p++) {
        if (sh_done) break;
        if (tid < 256) hist[tid] = 0u;
        __syncthreads();
        int remK = sh_remK;

        for (int m = 0; m < 10; m++) {
            int i = tid + (m << 10);
            bool act = (i < Nc);
            unsigned bin = 0;
            bool match = false;
            if (act) {
                unsigned long long key = (((unsigned long long)SC[i]) << 32) | (unsigned)(Nc - 1 - i);
                match = (p == 0) || ((key >> (S[p] + 8)) == (prefix >> (S[p] + 8)));
                bin = (unsigned)((key >> S[p]) & 255ull);
            }
            unsigned am = __ballot_sync(0xffffffffu, act && match);
            if (act && match) {
                unsigned peers = __match_any_sync(am, bin);
                if (lane == __ffs(peers) - 1) atomicAdd(&hist[bin], (unsigned)__popc(peers));
            }
        }
        __syncthreads();

        // suffix scan: cum[t] = sum_{v>=t} hist[v]
        if (tid < 256) cum[tid] = hist[tid];
        if (tid == 0) cum[256] = 0u;
        __syncthreads();
        for (int off = 1; off < 256; off <<= 1) {
            unsigned v = 0;
            if (tid < 256 && tid + off < 256) v = cum[tid + off];
            __syncthreads();
            if (tid < 256) cum[tid] += v;
            __syncthreads();
        }
        if (tid < 256) {
            unsigned above = (tid == 255) ? 0u : cum[tid + 1];
            if (cum[tid] >= (unsigned)remK && above < (unsigned)remK) sh_bsel = tid;
        }
        __syncthreads();
        int bsel = sh_bsel;
        prefix |= ((unsigned long long)(unsigned)bsel) << S[p];
        if (tid == 0) {
            unsigned above = (bsel == 255) ? 0u : cum[bsel + 1];
            int newRem = remK - (int)above;
            sh_remK = newRem;
            if ((int)hist[bsel] == newRem) sh_done = 1;  // whole bin selected: lower bytes stay 0
        }
        __syncthreads();
    }

    // fused selection for this batch (warp-aggregated atomics; all lanes stay convergent)
    unsigned long long thr = prefix;
    for (int m = 0; m < 10; m++) {
        int i = tid + (m << 10);
        bool act = (i < Nc);
        bool s = false;
        int od = 0;
        if (act) {
            unsigned long long key = (((unsigned long long)SC[i]) << 32) | (unsigned)(Nc - 1 - i);
            s = (key >= thr);
            g_sel[b * Nc + i] = s ? (unsigned char)1 : (unsigned char)0;
            if (s) od = g_outdeg[i];
        }
        bool upd = s && (od > 0);
        unsigned long long contrib = upd ?
            (unsigned long long)((double)logf((float)od + 1.f) * 4294967296.0) : 0ull;
#pragma unroll
        for (int off = 16; off > 0; off >>= 1)
            contrib += __shfl_down_sync(0xffffffffu, contrib, off);
        if (lane == 0 && contrib) atomicAdd(&g_sumlogA[l], contrib);

        unsigned um = __ballot_sync(0xffffffffu, upd);
        if (um) {
            int leader = __ffs(um) - 1;
            int baseU = 0;
            if (lane == leader) baseU = atomicAdd(&g_UcntA[l], __popc(um));
            baseU = __shfl_sync(0xffffffffu, baseU, leader);
            if (upd) {
                int v = b * Nc + i;
                g_Ulist[baseU + __popc(um & ((1u << lane) - 1u))] = v;
                if (atomicExch(&g_dirty[v], 1) == 0) {
                    int p2 = atomicAdd(&g_Dcnt, 1);
                    g_Dlist[p2] = v;
                }
            }
        }
    }
}

// ------------------------ Q fill over Ulist (every selected edge-source is in it) ------------------------
__global__ void __launch_bounds__(128) k_qfill(int l, const float* __restrict__ Wb) {
    __shared__ __align__(16) float hs[Dc][8];
    __shared__ int nds[8];
    int cnt = g_UcntA[l];
    int base = blockIdx.x * 8;
    if (base >= cnt) return;
    int nt = min(8, cnt - base);
    int k = threadIdx.x;
    if (k < nt) nds[k] = g_Ulist[base + k];
    __syncthreads();
#pragma unroll
    for (int t = 0; t < 8; t++) hs[k][t] = (t < nt) ? g_hidden[nds[t] * Dc + k] : 0.f;
    __syncthreads();
    unsigned long long acc[4] = {0ull, 0ull, 0ull, 0ull};
    for (int j = 0; j < Dc; j++) {
        float w = Wb[j * Dc + k];
        unsigned long long wp = pk(w, w);
        ulonglong2 h01 = *(const ulonglong2*)&hs[j][0];
        ulonglong2 h23 = *(const ulonglong2*)&hs[j][4];
        acc[0] = ffma2(h01.x, wp, acc[0]); acc[1] = ffma2(h01.y, wp, acc[1]);
        acc[2] = ffma2(h23.x, wp, acc[2]); acc[3] = ffma2(h23.y, wp, acc[3]);
    }
#pragma unroll
    for (int p = 0; p < 4; p++) {
        float lo, hi; upk(acc[p], lo, hi);
        int t0 = 2 * p, t1 = t0 + 1;
        if (t0 < nt) g_Q[nds[t0] * Dc + k] = lo;
        if (t1 < nt) g_Q[nds[t1] * Dc + k] = hi;
    }
}

// ------------------------ PNA conv + residual, 16 nodes/block, 256 thr, f32x2 ------------------------
__global__ void __launch_bounds__(256) k_conv(int l,
                                              const float* __restrict__ preWtop,
                                              const float* __restrict__ preb,
                                              const float* __restrict__ postW,
                                              const float* __restrict__ postb,
                                              const float* __restrict__ outW,
                                              const float* __restrict__ outb) {
    extern __shared__ float sh[];
    float* hs = sh;                 // [128][AGS]
    float* cs = sh + 128 * AGS;     // [128][AGS]
    float* os = sh + 256 * AGS;     // [128][AGS]
    float* ag = sh + 384 * AGS;     // [512][AGS]  (mean|max|min|std)
    __shared__ int un[16];
    __shared__ float d1s[16], d2s[16];

    int ucnt = g_UcntA[l];
    int base = blockIdx.x * 16;
    if (base >= ucnt) return;
    int nt = min(16, ucnt - base);
    int tid = threadIdx.x, k = tid & 127, half = tid >> 7;

    if (tid < nt) un[tid] = g_Ulist[base + tid];
    else if (tid < 16) un[tid] = 0;
    __syncthreads();

    if (tid < 16) {
        float d1 = 0.f, d2 = 0.f;
        if (tid < nt) {
            double sl = (double)g_sumlogA[l] / 4294967296.0;
            float avl = (float)((sl + (double)(BNc - ucnt) * 0.6931471805599453) / (double)BNc);
            int i = un[tid] % Nc;
            float logd = logf((float)g_outdeg[i] + 1.f);
            d1 = logd / avl;
            d2 = avl / logd;
        }
        d1s[tid] = d1; d2s[tid] = d2;
    }
#pragma unroll
    for (int j2 = 0; j2 < 8; j2++) {
        int t = 8 * half + j2;
        hs[k * AGS + t] = (t < nt) ? g_hidden[un[t] * Dc + k] : 0.f;
    }
    __syncthreads();

    // pre: c = hidden @ pre_W[0:D] + pre_b  (each half: its 8 nodes, 4 packed pairs)
    {
        unsigned long long acc[4] = {0ull, 0ull, 0ull, 0ull};
        for (int j = 0; j < Dc; j++) {
            float w = preWtop[j * Dc + k];
            unsigned long long wp = pk(w, w);
            ulonglong2 h01 = *(const ulonglong2*)&hs[j * AGS + 8 * half];
            ulonglong2 h23 = *(const ulonglong2*)&hs[j * AGS + 8 * half + 4];
            acc[0] = ffma2(h01.x, wp, acc[0]); acc[1] = ffma2(h01.y, wp, acc[1]);
            acc[2] = ffma2(h23.x, wp, acc[2]); acc[3] = ffma2(h23.y, wp, acc[3]);
        }
        float pb = preb[k];
#pragma unroll
        for (int p = 0; p < 4; p++) {
            float lo, hi; upk(acc[p], lo, hi);
            cs[k * AGS + 8 * half + 2 * p]     = lo + pb;
            cs[k * AGS + 8 * half + 2 * p + 1] = hi + pb;
        }
    }
    __syncthreads();

    // aggregation per node: m = c_dst + Q[src] over selected in-edges
#pragma unroll
    for (int j2 = 0; j2 < 8; j2++) {
        int t = 8 * half + j2;
        float mean = 0.f, mx = 0.f, mn = 0.f, st = 0.f;
        if (t < nt) {
            int node = un[t];
            int bb = node / Nc;
            int i = node - bb * Nc;
            float c = cs[k * AGS + t];
            float s1 = 0.f, s2 = 0.f;
            float Mx = -INFINITY, Mn = INFINITY;
            int ce = 0;
            int e0 = g_inoff[i], e1 = g_inoff[i + 1];
            for (int e = e0; e < e1; e++) {
                int sg = bb * Nc + g_insrc[e];
                if (g_sel[sg]) {
                    float m = c + g_Q[sg * Dc + k];
                    s1 += m; s2 += m * m;
                    Mx = fmaxf(Mx, m); Mn = fminf(Mn, m);
                    ce++;
                }
            }
            float denom = (float)max(ce, 1);
            mean = s1 / denom;
            float var = fmaxf(s2 / denom - mean * mean, 0.f);
            st = sqrtf(var + EPSc);
            mx = ce ? Mx : 0.f;
            mn = ce ? Mn : 0.f;
        }
        ag[k * AGS + t]         = mean;
        ag[(128 + k) * AGS + t] = mx;
        ag[(256 + k) * AGS + t] = mn;
        ag[(384 + k) * AGS + t] = st;
    }
    __syncthreads();

    // post: agg12 @ post_W + post_b, scalers folded into the packed weight
    {
        unsigned long long d1p[4], d2p[4];
#pragma unroll
        for (int p = 0; p < 4; p++) {
            d1p[p] = pk(d1s[8 * half + 2 * p], d1s[8 * half + 2 * p + 1]);
            d2p[p] = pk(d2s[8 * half + 2 * p], d2s[8 * half + 2 * p + 1]);
        }
        unsigned long long acc[4] = {0ull, 0ull, 0ull, 0ull};
        for (int j = 0; j < 512; j++) {
            float w0 = postW[j * Dc + k];
            float w1 = postW[(512 + j) * Dc + k];
            float w2 = postW[(1024 + j) * Dc + k];
            unsigned long long w0p = pk(w0, w0), w1p = pk(w1, w1), w2p = pk(w2, w2);
            ulonglong2 a01 = *(const ulonglong2*)&ag[j * AGS + 8 * half];
            ulonglong2 a23 = *(const ulonglong2*)&ag[j * AGS + 8 * half + 4];
            unsigned long long wt;
            wt = ffma2(d1p[0], w1p, ffma2(d2p[0], w2p, w0p)); acc[0] = ffma2(a01.x, wt, acc[0]);
            wt = ffma2(d1p[1], w1p, ffma2(d2p[1], w2p, w0p)); acc[1] = ffma2(a01.y, wt, acc[1]);
            wt = ffma2(d1p[2], w1p, ffma2(d2p[2], w2p, w0p)); acc[2] = ffma2(a23.x, wt, acc[2]);
            wt = ffma2(d1p[3], w1p, ffma2(d2p[3], w2p, w0p)); acc[3] = ffma2(a23.y, wt, acc[3]);
        }
        float pob = postb[k];
#pragma unroll
        for (int p = 0; p < 4; p++) {
            float lo, hi; upk(acc[p], lo, hi);
            os[k * AGS + 8 * half + 2 * p]     = lo + pob;
            os[k * AGS + 8 * half + 2 * p + 1] = hi + pob;
        }
    }
    __syncthreads();

    // out: out1 @ out_W + out_b; residual add
    {
        unsigned long long acc[4] = {0ull, 0ull, 0ull, 0ull};
        for (int j = 0; j < Dc; j++) {
            float w = outW[j * Dc + k];
            unsigned long long wp = pk(w, w);
            ulonglong2 o01 = *(const ulonglong2*)&os[j * AGS + 8 * half];
            ulonglong2 o23 = *(const ulonglong2*)&os[j * AGS + 8 * half + 4];
            acc[0] = ffma2(o01.x, wp, acc[0]); acc[1] = ffma2(o01.y, wp, acc[1]);
            acc[2] = ffma2(o23.x, wp, acc[2]); acc[3] = ffma2(o23.y, wp, acc[3]);
        }
        float ob = outb[k];
#pragma unroll
        for (int p = 0; p < 4; p++) {
            float lo, hi; upk(acc[p], lo, hi);
            int t0 = 8 * half + 2 * p, t1 = t0 + 1;
            if (t0 < nt) g_hidden[un[t0] * Dc + k] += lo + ob;
            if (t1 < nt) g_hidden[un[t1] * Dc + k] += hi + ob;
        }
    }
}

// ------------------------ scoring (mode 0: Dlist + clean-fill blocks; 2: readout -> out) ----------
__global__ void __launch_bounds__(128) k_score(int mode,
                                               const float* __restrict__ linW,
                                               const float* __restrict__ m1W,
                                               const float* __restrict__ m1b,
                                               const float* __restrict__ m2W,
                                               const float* __restrict__ m2b,
                                               float* __restrict__ out) {
    int blk = blockIdx.x, k = threadIdx.x;
    if (mode == 0 && blk >= SCORE_BLKS) {
        int j = (blk - SCORE_BLKS) * 128 + k;
        if (j < BNc && g_dirty[j] == 0) g_score[j] = g_szero;
        return;
    }
    const int* list = (mode == 0) ? g_Dlist : g_tidx;
    int cnt = (mode == 0) ? g_Dcnt : (Bc * NEGc);
    int base = blk * 8;
    if (base >= cnt) return;
    int nt = min(8, cnt - base);

    __shared__ __align__(16) float hs[Dc][8];
    __shared__ __align__(16) float xs[Dc][8];
    __shared__ float red[Dc][8];
    __shared__ int nds[8];
    if (k < nt) nds[k] = list[base + k];
    __syncthreads();
#pragma unroll
    for (int t = 0; t < 8; t++) hs[k][t] = (t < nt) ? g_hidden[nds[t] * Dc + k] : 0.f;
    __syncthreads();

    unsigned long long a1[4] = {0ull, 0ull, 0ull, 0ull};
    for (int j = 0; j < Dc; j++) {
        float w = linW[j * Dc + k];
        unsigned long long wp = pk(w, w);
        ulonglong2 h01 = *(const ulonglong2*)&hs[j][0];
        ulonglong2 h23 = *(const ulonglong2*)&hs[j][4];
        a1[0] = ffma2(h01.x, wp, a1[0]); a1[1] = ffma2(h01.y, wp, a1[1]);
        a1[2] = ffma2(h23.x, wp, a1[2]); a1[3] = ffma2(h23.y, wp, a1[3]);
    }
#pragma unroll
    for (int p = 0; p < 4; p++) {
        float lo, hi; upk(a1[p], lo, hi);
        int t0 = 2 * p, t1 = t0 + 1;
        float x0 = 0.f, x1 = 0.f;
        if (t0 < nt) { int bb = nds[t0] / Nc; x0 = (lo + g_rellin[bb * Dc + k]) * hs[k][t0]; }
        if (t1 < nt) { int bb = nds[t1] / Nc; x1 = (hi + g_rellin[bb * Dc + k]) * hs[k][t1]; }
        xs[k][t0] = x0; xs[k][t1] = x1;
    }
    __syncthreads();

    unsigned long long a2[4] = {0ull, 0ull, 0ull, 0ull};
    for (int j = 0; j < Dc; j++) {
        float w = m1W[j * Dc + k];
        unsigned long long wp = pk(w, w);
        ulonglong2 x01 = *(const ulonglong2*)&xs[j][0];
        ulonglong2 x23 = *(const ulonglong2*)&xs[j][4];
        a2[0] = ffma2(x01.x, wp, a2[0]); a2[1] = ffma2(x01.y, wp, a2[1]);
        a2[2] = ffma2(x23.x, wp, a2[2]); a2[3] = ffma2(x23.y, wp, a2[3]);
    }
    float mb = m1b[k], w2 = m2W[k];
#pragma unroll
    for (int p = 0; p < 4; p++) {
        float lo, hi; upk(a2[p], lo, hi);
        red[k][2 * p]     = fmaxf(lo + mb, 0.f) * w2;
        red[k][2 * p + 1] = fmaxf(hi + mb, 0.f) * w2;
    }
    __syncthreads();
    for (int s = 64; s > 0; s >>= 1) {
        if (k < s) {
#pragma unroll
            for (int t = 0; t < 8; t++) red[k][t] += red[k + s][t];
        }
        __syncthreads();
    }
    if (k < nt) {
        float r = red[0][k] + m2b[0];
        if (mode == 0) g_score[nds[k]] = r;
        else out[base + k] = r;
    }
}

// ------------------------ host ------------------------
extern "C" void kernel_launch(void* const* d_in, const int* in_sizes, int n_in,
                              void* d_out, int out_size) {
    const int*   hI    = (const int*)d_in[0];
    const int*   rI    = (const int*)d_in[1];
    const int*   tI    = (const int*)d_in[2];
    const float* HS    = (const float*)d_in[3];
    const int*   EI    = (const int*)d_in[4];
    const float* RE    = (const float*)d_in[5];
    const float* linW  = (const float*)d_in[6];
    const float* linb  = (const float*)d_in[7];
    const float* m1W   = (const float*)d_in[8];
    const float* m1b   = (const float*)d_in[9];
    const float* m2W   = (const float*)d_in[10];
    const float* m2b   = (const float*)d_in[11];
    const float* preW  = (const float*)d_in[12];
    const float* preb  = (const float*)d_in[13];
    const float* postW = (const float*)d_in[14];
    const float* postb = (const float*)d_in[15];
    const float* outW  = (const float*)d_in[16];
    const float* outb  = (const float*)d_in[17];
    float* out = (float*)d_out;

    const int CONV_SMEM = 896 * AGS * 4;   // 71680 B
    cudaFuncSetAttribute(k_conv, cudaFuncAttributeMaxDynamicSharedMemorySize, CONV_SMEM);

    k_zero<<<(BNc * Dc + 255) / 256, 256>>>();
    k_deg<<<(Ec + 255) / 256, 256>>>(EI);
    k_scan<<<1, 1024>>>();
    k_fill<<<(Ec + 255) / 256, 256>>>(EI);
    k_prep1<<<3, 128>>>(hI, rI, tI, HS, RE, linW, linb, m1b, m2W, m2b);
    k_prep2<<<2, 128>>>(hI, tI, HS, linW, m1W, m1b, m2W, m2b);

    for (int l = 0; l < Lc; l++) {
        k_topk<<<Bc, 1024, Nc * sizeof(unsigned)>>>(l);
        k_qfill<<<UMAXc / 8, 128>>>(l, preW + l * 2 * Dc * Dc + Dc * Dc);
        k_conv<<<UMAXc / 16, 256, CONV_SMEM>>>(l, preW + l * 2 * Dc * Dc, preb + l * Dc,
                                               postW + l * 12 * Dc * Dc, postb + l * Dc,
                                               outW + l * Dc * Dc, outb + l * Dc);
        if (l < Lc - 1)
            k_score<<<SCORE_BLKS + FILL_BLKS, 128>>>(0, linW, m1W, m1b, m2W, m2b, out);
        else
            k_score<<<(Bc * NEGc + 7) / 8, 128>>>(2, linW, m1W, m1b, m2W, m2b, out);
    }
}